// round 3
// baseline (speedup 1.0000x reference)
#include <cuda_runtime.h>
#include <math.h>

#define B     40000
#define D     128
#define D4    (D/4)
#define ND    200000
#define ESUB  320000
#define ESUP  1280000

// Scratch (static device globals — no allocation in kernel_launch)
__device__ float g_diff[(size_t)B * D];
__device__ float g_dots[3];   // [0]=sum(in*old), [1]=sum(in^2), [2]=sum(old^2)

// ---------------------------------------------------------------------------
__global__ void zero_dots_kernel() {
    if (threadIdx.x < 3) g_dots[threadIdx.x] = 0.0f;
}

// Gather old rows, compute diff into g_diff, accumulate the three dot products.
__global__ void gather_diff_dot_kernel(const float* __restrict__ inputs,
                                       const float* __restrict__ old_act,
                                       const int*   __restrict__ fields) {
    __shared__ float s_red[3][8];  // per-warp partials, up to 8 warps/block
    const int tid   = blockIdx.x * blockDim.x + threadIdx.x;
    const int nthr  = gridDim.x * blockDim.x;
    const int total = B * D4;

    float dot = 0.0f, nin = 0.0f, nold = 0.0f;

    const float4* in4  = (const float4*)inputs;
    const float4* old4 = (const float4*)old_act;
    float4*       df4  = (float4*)g_diff;   // device-code reference: real address

    for (int i = tid; i < total; i += nthr) {
        const int row = i / D4;
        const int c4  = i - row * D4;
        const int f   = __ldg(&fields[row]);
        float4 a = in4[i];
        float4 o = old4[(size_t)f * D4 + c4];
        float4 d;
        d.x = a.x - o.x; d.y = a.y - o.y; d.z = a.z - o.z; d.w = a.w - o.w;
        df4[i] = d;
        dot  += a.x*o.x + a.y*o.y + a.z*o.z + a.w*o.w;
        nin  += a.x*a.x + a.y*a.y + a.z*a.z + a.w*a.w;
        nold += o.x*o.x + o.y*o.y + o.z*o.z + o.w*o.w;
    }

    // warp reduce
    #pragma unroll
    for (int off = 16; off > 0; off >>= 1) {
        dot  += __shfl_down_sync(0xffffffffu, dot,  off);
        nin  += __shfl_down_sync(0xffffffffu, nin,  off);
        nold += __shfl_down_sync(0xffffffffu, nold, off);
    }
    const int lane = threadIdx.x & 31;
    const int wid  = threadIdx.x >> 5;
    if (lane == 0) { s_red[0][wid] = dot; s_red[1][wid] = nin; s_red[2][wid] = nold; }
    __syncthreads();
    if (wid == 0) {
        const int nw = blockDim.x >> 5;
        float v0 = (lane < nw) ? s_red[0][lane] : 0.0f;
        float v1 = (lane < nw) ? s_red[1][lane] : 0.0f;
        float v2 = (lane < nw) ? s_red[2][lane] : 0.0f;
        #pragma unroll
        for (int off = 16; off > 0; off >>= 1) {
            v0 += __shfl_down_sync(0xffffffffu, v0, off);
            v1 += __shfl_down_sync(0xffffffffu, v1, off);
            v2 += __shfl_down_sync(0xffffffffu, v2, off);
        }
        if (lane == 0) {
            atomicAdd(&g_dots[0], v0);
            atomicAdd(&g_dots[1], v1);
            atomicAdd(&g_dots[2], v2);
        }
    }
}

__global__ void sim_kernel(float* __restrict__ out, int out_size) {
    if (out_size > B * D) {
        out[B * D] = g_dots[0] / (sqrtf(g_dots[1]) * sqrtf(g_dots[2]));
    }
}

// ---------------------------------------------------------------------------
// Fused COO SpMM scatter over both edge lists.
// One warp per edge; 32 lanes x float4 cover the 128-float row.
// g_diff is referenced in DEVICE code here (correct device address).
__global__ void spmm_fused_kernel(const int*   __restrict__ sub_rows,
                                  const int*   __restrict__ sub_cols,
                                  const float* __restrict__ sub_vals,
                                  const int*   __restrict__ sup_rows,
                                  const int*   __restrict__ sup_cols,
                                  const float* __restrict__ sup_vals,
                                  const float* __restrict__ old_act,
                                  float*       __restrict__ out) {
    const int gwarp  = (blockIdx.x * blockDim.x + threadIdx.x) >> 5;
    const int lane   = threadIdx.x & 31;
    const int nwarps = (gridDim.x * blockDim.x) >> 5;
    const int total  = ESUB + ESUP;

    for (int e = gwarp; e < total; e += nwarps) {
        int r, c; float v;
        const float* __restrict__ src;
        if (e < ESUB) {
            r = __ldg(&sub_rows[e]);
            c = __ldg(&sub_cols[e]);
            v = __ldg(&sub_vals[e]);
            src = g_diff;                 // device-side symbol: valid address
        } else {
            const int i = e - ESUB;
            r = __ldg(&sup_rows[i]);
            c = __ldg(&sup_cols[i]);
            v = __ldg(&sup_vals[i]);
            src = old_act;
        }
        const float4 s = ((const float4*)(src + (size_t)c * D))[lane];
        float4 x;
        x.x = s.x * v; x.y = s.y * v; x.z = s.z * v; x.w = s.w * v;
        float* o = out + (size_t)r * D + lane * 4;
        asm volatile("red.global.add.v4.f32 [%0], {%1, %2, %3, %4};"
                     :: "l"(o), "f"(x.x), "f"(x.y), "f"(x.z), "f"(x.w)
                     : "memory");
    }
}

// ---------------------------------------------------------------------------
extern "C" void kernel_launch(void* const* d_in, const int* in_sizes, int n_in,
                              void* d_out, int out_size) {
    const float* inputs   = (const float*)d_in[0];   // [B, D]
    const float* old_act  = (const float*)d_in[1];   // [ND, D]
    const int*   fields   = (const int*)  d_in[2];   // [B]
    const int*   sub_rows = (const int*)  d_in[3];   // [ESUB]
    const int*   sub_cols = (const int*)  d_in[4];
    const float* sub_vals = (const float*)d_in[5];
    const int*   sup_rows = (const int*)  d_in[6];   // [ESUP]
    const int*   sup_cols = (const int*)  d_in[7];
    const float* sup_vals = (const float*)d_in[8];
    float* out = (float*)d_out;

    // Zero the accumulation region (first B*D elements of out).
    size_t zcount = (size_t)((out_size < B * D) ? out_size : B * D);
    cudaMemsetAsync(d_out, 0, zcount * sizeof(float));

    zero_dots_kernel<<<1, 32>>>();

    gather_diff_dot_kernel<<<2048, 256>>>(inputs, old_act, fields);

    sim_kernel<<<1, 1>>>(out, out_size);

    // Fused SpMM: subsampled_support @ diff  +  support @ old_activation
    spmm_fused_kernel<<<148 * 16, 256>>>(sub_rows, sub_cols, sub_vals,
                                         sup_rows, sup_cols, sup_vals,
                                         old_act, out);
}